// round 16
// baseline (speedup 1.0000x reference)
#include <cuda_runtime.h>
#include <cuda_fp16.h>
#include <cstdint>
#include <float.h>

#define NB 2048     // batch
#define NH 50       // history
#define ND 128      // dim (K)
#define NV 100000   // vocab
#define NK 10       // top_k

#define TM 128      // rowtile (batch)
#define TN 64       // coltile (vocab)
#define NCOLT ((NV + TN - 1) / TN)   // 1563
#define NCG 18                       // column groups
#define NRT (NB / TM)                // 16  -> 288 CTAs, 2/SM
#define THREADS 128                  // 4 warps; warp tile 64x32 (R12 shape)

#define SC   1024.0f
#define ISC2 (1.0f / (1024.0f * 1024.0f))

#define HPITCH 136                   // smem pitch in halves (272 B rows)

// smem (halves): A1 [128][136], A2, B1 [64][136], B2  = 104448 B per CTA (occ 2)
#define OFF_A1 0
#define OFF_A2 (TM * HPITCH)
#define OFF_B1 (2 * TM * HPITCH)
#define OFF_B2 (2 * TM * HPITCH + TN * HPITCH)
#define SMEM_HALVES (2 * TM * HPITCH + 2 * TN * HPITCH)

__device__ __align__(16) __half g_a1[NB * ND];
__device__ __align__(16) __half g_a2[NB * ND];
__device__ float g_aux[(long)NB * NCOLT];    // per-(row, coltile) max of logits

__device__ __forceinline__ int fkey(float f) {
    int u = __float_as_int(f);
    return (u >= 0) ? u : (u ^ 0x7fffffff);
}
__device__ __forceinline__ float ikey(int k) {
    return (k >= 0) ? __int_as_float(k) : __int_as_float(k ^ 0x7fffffff);
}

__device__ __forceinline__ void mma16(float (&d)[4], const uint32_t (&a)[4],
                                      uint32_t b0, uint32_t b1) {
    asm("mma.sync.aligned.m16n8k16.row.col.f32.f16.f16.f32 "
        "{%0,%1,%2,%3}, {%4,%5,%6,%7}, {%8,%9}, {%0,%1,%2,%3};"
        : "+f"(d[0]), "+f"(d[1]), "+f"(d[2]), "+f"(d[3])
        : "r"(a[0]), "r"(a[1]), "r"(a[2]), "r"(a[3]), "r"(b0), "r"(b1));
}

__device__ __forceinline__ void ldsm4(uint32_t (&r)[4], uint32_t addr) {
    asm volatile("ldmatrix.sync.aligned.m8n8.x4.shared.b16 {%0,%1,%2,%3}, [%4];"
        : "=r"(r[0]), "=r"(r[1]), "=r"(r[2]), "=r"(r[3]) : "r"(addr));
}

__device__ __forceinline__ void hsplit(float a, __half& h1, __half& h2) {
    float w = a * SC;
    h1 = __float2half_rn(w);
    h2 = __float2half_rn(w - __half2float(h1));
}

// ---------------------------------------------------------------------------
// Kernel 1: ctx = mean(ctab[ids]) @ W + b, then scaled fp16 hi/lo split
// ---------------------------------------------------------------------------
__global__ void ctx_kernel(const int* __restrict__ ids,
                           const float* __restrict__ ctab,
                           const float* __restrict__ W,
                           const float* __restrict__ bias) {
    int row = blockIdx.x;
    int d = threadIdx.x;
    __shared__ float pooled[ND];

    float s = 0.0f;
    #pragma unroll 5
    for (int h = 0; h < NH; ++h) {
        int id = ids[row * NH + h];
        s += ctab[(long)id * ND + d];
    }
    pooled[d] = s * (1.0f / (float)NH);
    __syncthreads();

    float acc = bias[d];
    #pragma unroll 8
    for (int i = 0; i < ND; ++i)
        acc = fmaf(pooled[i], W[i * ND + d], acc);

    __half h1, h2;
    hsplit(acc, h1, h2);
    g_a1[row * ND + d] = h1;
    g_a2[row * ND + d] = h2;
}

// ---------------------------------------------------------------------------
// Kernel 2: logits = ctx @ labelT via 3x FP16 mma.sync (R12 per-warp engine)
// TM=128, 128 threads, occupancy 2: co-resident CTA hides fill/barrier
// exposure. Serial fill (no prefetch regs -> no spills).
// ---------------------------------------------------------------------------
extern __shared__ __half sm_h[];

__global__ __launch_bounds__(THREADS, 2)
void gemm_kernel(const float* __restrict__ label, float* __restrict__ out) {
    const int tid  = threadIdx.x;
    const int lane = tid & 31;
    const int wid  = tid >> 5;
    const int r0   = blockIdx.y * TM;

    __shared__ int s_rowmax[TM];
    s_rowmax[tid] = 0x80000000;   // 128 threads, TM=128

    // ---- Load resident A rowtile (pre-split fp16): one row per thread ----
    {
        const uint4* p1 = (const uint4*)(g_a1 + (long)(r0 + tid) * ND);
        const uint4* p2 = (const uint4*)(g_a2 + (long)(r0 + tid) * ND);
        uint4* d1 = (uint4*)(sm_h + OFF_A1 + tid * HPITCH);
        uint4* d2 = (uint4*)(sm_h + OFF_A2 + tid * HPITCH);
        #pragma unroll
        for (int j = 0; j < 16; ++j) { d1[j] = p1[j]; d2[j] = p2[j]; }
    }

    // ---- ldmatrix base addresses (bytes) ----
    const uint32_t sbase = (uint32_t)__cvta_generic_to_shared(sm_h);
    uint32_t aA1[4], aA2[4], bB1[2], bB2[2];
    {
        int jrowA = ((lane >> 3) & 1) * 8 + (lane & 7);
        int kcolA = (lane >> 4) * 8;
        #pragma unroll
        for (int mi = 0; mi < 4; ++mi) {
            int rowA = (wid >> 1) * 64 + mi * 16 + jrowA;
            aA1[mi] = sbase + (uint32_t)(OFF_A1 + rowA * HPITCH + kcolA) * 2u;
            aA2[mi] = sbase + (uint32_t)(OFF_A2 + rowA * HPITCH + kcolA) * 2u;
        }
        int jrowB = (lane >> 4) * 8 + (lane & 7);
        int kcolB = ((lane >> 3) & 1) * 8;
        #pragma unroll
        for (int p = 0; p < 2; ++p) {
            int rowB = (wid & 1) * 32 + p * 16 + jrowB;
            bB1[p] = sbase + (uint32_t)(OFF_B1 + rowB * HPITCH + kcolB) * 2u;
            bB2[p] = sbase + (uint32_t)(OFF_B2 + rowB * HPITCH + kcolB) * 2u;
        }
    }

    // B fill mapping: 128 threads, row pn = tid>>1 (2 threads/row), 16 float4 each
    const int pn = tid >> 1;
    const int pd = (tid & 1) * 64;      // float col base (64 floats per thread)

    int ct = blockIdx.x;
    while (true) {
        // ---- serial fill: LDG + split + STS (exposure hidden by co-CTA) ----
        __syncthreads();   // prior tile's frag reads done
        {
            long gn = (long)ct * TN + pn;
            if (gn > NV - 1) gn = NV - 1;             // clamp; never consumed
            const float4* src = (const float4*)(label + gn * ND + pd);
            __half* b1 = sm_h + OFF_B1 + pn * HPITCH + pd;
            __half* b2 = sm_h + OFF_B2 + pn * HPITCH + pd;
            #pragma unroll
            for (int j = 0; j < 16; ++j) {
                float4 v = src[j];
                __half hx1, hx2, hy1, hy2, hz1, hz2, hw1, hw2;
                hsplit(v.x, hx1, hx2); hsplit(v.y, hy1, hy2);
                hsplit(v.z, hz1, hz2); hsplit(v.w, hw1, hw2);
                __half2* q1 = (__half2*)(b1 + j * 4);
                __half2* q2 = (__half2*)(b2 + j * 4);
                q1[0] = __halves2half2(hx1, hy1);
                q1[1] = __halves2half2(hz1, hw1);
                q2[0] = __halves2half2(hx2, hy2);
                q2[1] = __halves2half2(hz2, hw2);
            }
        }
        __syncthreads();

        // ---- compute tile (register-double-buffered frags, R12 engine) ----
        uint32_t A1f[2][4][4], A2f[2][4][4], B1f[2][2][4], B2f[2][2][4];
        float acc[4][4][4];
        #pragma unroll
        for (int mi = 0; mi < 4; ++mi)
            #pragma unroll
            for (int ni = 0; ni < 4; ++ni)
                #pragma unroll
                for (int q = 0; q < 4; ++q) acc[mi][ni][q] = 0.0f;

        #pragma unroll
        for (int mi = 0; mi < 4; ++mi) { ldsm4(A1f[0][mi], aA1[mi]); ldsm4(A2f[0][mi], aA2[mi]); }
        ldsm4(B1f[0][0], bB1[0]); ldsm4(B1f[0][1], bB1[1]);
        ldsm4(B2f[0][0], bB2[0]); ldsm4(B2f[0][1], bB2[1]);

        #pragma unroll
        for (int ks = 0; ks < 8; ++ks) {
            const int kcur = ks & 1;
            if (ks < 7) {
                const int nxt = kcur ^ 1;
                const uint32_t ko = (uint32_t)(ks + 1) * 32u;   // 16 halves = 32 B
                #pragma unroll
                for (int mi = 0; mi < 4; ++mi) {
                    ldsm4(A1f[nxt][mi], aA1[mi] + ko);
                    ldsm4(A2f[nxt][mi], aA2[mi] + ko);
                }
                ldsm4(B1f[nxt][0], bB1[0] + ko); ldsm4(B1f[nxt][1], bB1[1] + ko);
                ldsm4(B2f[nxt][0], bB2[0] + ko); ldsm4(B2f[nxt][1], bB2[1] + ko);
            }
            #pragma unroll
            for (int mi = 0; mi < 4; ++mi)
                #pragma unroll
                for (int p = 0; p < 2; ++p) {
                    mma16(acc[mi][2*p],   A1f[kcur][mi], B1f[kcur][p][0], B1f[kcur][p][1]);
                    mma16(acc[mi][2*p+1], A1f[kcur][mi], B1f[kcur][p][2], B1f[kcur][p][3]);
                    mma16(acc[mi][2*p],   A1f[kcur][mi], B2f[kcur][p][0], B2f[kcur][p][1]);
                    mma16(acc[mi][2*p+1], A1f[kcur][mi], B2f[kcur][p][2], B2f[kcur][p][3]);
                    mma16(acc[mi][2*p],   A2f[kcur][mi], B1f[kcur][p][0], B1f[kcur][p][1]);
                    mma16(acc[mi][2*p+1], A2f[kcur][mi], B1f[kcur][p][2], B1f[kcur][p][3]);
                }
        }

        // ---- epilogue: un-scale (exact 2^-20), store, tile-max sideband ----
        {
            const int n0 = ct * TN;
            #pragma unroll
            for (int mi = 0; mi < 4; ++mi) {
                int rloc0 = (wid >> 1) * 64 + mi * 16 + (lane >> 2);
                long rg = r0 + rloc0;
                float* o0 = out + rg * (long)NV;
                float* o1 = o0 + 8l * NV;
                float m0 = -FLT_MAX, m1 = -FLT_MAX;
                #pragma unroll
                for (int ni = 0; ni < 4; ++ni) {
                    int cg = n0 + (wid & 1) * 32 + ni * 8 + 2 * (lane & 3);
                    float v0 = acc[mi][ni][0] * ISC2, v1 = acc[mi][ni][1] * ISC2;
                    float v2 = acc[mi][ni][2] * ISC2, v3 = acc[mi][ni][3] * ISC2;
                    if (cg < NV) {
                        *(float2*)(o0 + cg) = make_float2(v0, v1);
                        *(float2*)(o1 + cg) = make_float2(v2, v3);
                    }
                    m0 = fmaxf(m0, fmaxf(v0, v1));
                    m1 = fmaxf(m1, fmaxf(v2, v3));
                }
                atomicMax(&s_rowmax[rloc0],     fkey(m0));
                atomicMax(&s_rowmax[rloc0 + 8], fkey(m1));
            }
        }
        __syncthreads();   // atomics done
        {
            g_aux[(long)(r0 + tid) * NCOLT + ct] = ikey(s_rowmax[tid]);
            s_rowmax[tid] = 0x80000000;
        }
        const int nct = ct + NCG;
        if (nct >= NCOLT) break;
        ct = nct;
        // loop-top __syncthreads() orders rowmax reset + frag reads vs refill
    }
}

// ---------------------------------------------------------------------------
// Kernel 3: pruned per-row top-10 using g_aux tile maxima.
// ---------------------------------------------------------------------------
#define T2 256

__global__ __launch_bounds__(T2)
void topk_kernel(const float* __restrict__ logits,
                 float* __restrict__ out_ids,
                 float* __restrict__ out_scores) {
    const int row = blockIdx.x;
    const int tid = threadIdx.x;

    __shared__ float sm[NCOLT];
    __shared__ float rv[T2];
    __shared__ int   ri[T2];
    __shared__ float tv[NK];
    __shared__ int   ti[NK];
    __shared__ float cand[TN];

    for (int j = tid; j < NCOLT; j += T2)
        sm[j] = g_aux[(long)row * NCOLT + j];
    if (tid < NK) { tv[tid] = -FLT_MAX; ti[tid] = 0; }
    __syncthreads();

    const float* lrow = logits + (long)row * NV;

    for (int round = 0; round < NCOLT; ++round) {
        float bv = -FLT_MAX; int bi = NCOLT;
        for (int j = tid; j < NCOLT; j += T2) {
            float v = sm[j];
            if (v > bv || (v == bv && j < bi)) { bv = v; bi = j; }
        }
        rv[tid] = bv; ri[tid] = bi;
        __syncthreads();
        #pragma unroll
        for (int s = T2 / 2; s > 0; s >>= 1) {
            if (tid < s) {
                float ov = rv[tid + s]; int oi = ri[tid + s];
                if (ov > rv[tid] || (ov == rv[tid] && oi < ri[tid])) {
                    rv[tid] = ov; ri[tid] = oi;
                }
            }
            __syncthreads();
        }
        float best = rv[0]; int bidx = ri[0];
        if (best < tv[NK - 1] || bidx >= NCOLT) break;

        if (tid < TN) {
            int c = bidx * TN + tid;
            cand[tid] = (c < NV) ? lrow[c] : -FLT_MAX;
        }
        __syncthreads();
        if (tid == 0) {
            #pragma unroll 4
            for (int c = 0; c < TN; ++c) {
                float v = cand[c];
                int   id = bidx * TN + c;
                if (v > tv[NK - 1] || (v == tv[NK - 1] && v > -FLT_MAX && id < ti[NK - 1])) {
                    tv[NK - 1] = v; ti[NK - 1] = id;
                    #pragma unroll
                    for (int j = NK - 1; j > 0; --j) {
                        bool sw = (tv[j] > tv[j - 1]) ||
                                  (tv[j] == tv[j - 1] && ti[j] < ti[j - 1]);
                        if (sw) {
                            float fv = tv[j]; tv[j] = tv[j - 1]; tv[j - 1] = fv;
                            int ii = ti[j]; ti[j] = ti[j - 1]; ti[j - 1] = ii;
                        }
                    }
                }
            }
            sm[bidx] = -FLT_MAX;
        }
        __syncthreads();
    }

    if (tid < NK) {
        out_ids[row * NK + tid]    = (float)ti[tid];
        out_scores[row * NK + tid] = tv[tid];
    }
}

// ---------------------------------------------------------------------------
// Launch
// ---------------------------------------------------------------------------
extern "C" void kernel_launch(void* const* d_in, const int* in_sizes, int n_in,
                              void* d_out, int out_size) {
    const int*   ids  = (const int*)d_in[0];
    const float* ctab = (const float*)d_in[1];
    const float* ltab = (const float*)d_in[2];
    const float* W    = (const float*)d_in[3];
    const float* bias = (const float*)d_in[4];

    float* out        = (float*)d_out;
    float* logits     = out;
    float* out_ids    = out + (long)NB * NV;
    float* out_scores = out_ids + NB * NK;

    ctx_kernel<<<NB, ND>>>(ids, ctab, W, bias);

    size_t smem = (size_t)SMEM_HALVES * 2;   // 104448 B per CTA -> 2 CTAs/SM
    cudaFuncSetAttribute(gemm_kernel, cudaFuncAttributeMaxDynamicSharedMemorySize, (int)smem);
    dim3 grid(NCG, NRT);
    gemm_kernel<<<grid, THREADS, smem>>>(ltab, logits);

    topk_kernel<<<NB, T2>>>(logits, out_ids, out_scores);
}

// round 17
// speedup vs baseline: 1.3454x; 1.3454x over previous
#include <cuda_runtime.h>
#include <cuda_fp16.h>
#include <cstdint>
#include <float.h>

#define NB 2048     // batch
#define NH 50       // history
#define ND 128      // dim (K)
#define NV 100000   // vocab
#define NK 10       // top_k

#define TM 256      // rowtile (batch)
#define TN 64       // coltile (vocab)
#define NCOLT ((NV + TN - 1) / TN)   // 1563
#define NCG 18                       // column groups
#define NRT (NB / TM)                // 8   -> 144 CTAs

#define SC   1024.0f
#define ISC2 (1.0f / (1024.0f * 1024.0f))

#define HPITCH 136                   // smem pitch in halves (272 B rows)

// smem (halves): A1 [256][136], A2, B1 [64][136], B2  = 174080 B
#define OFF_A1 0
#define OFF_A2 (TM * HPITCH)
#define OFF_B1 (2 * TM * HPITCH)
#define OFF_B2 (2 * TM * HPITCH + TN * HPITCH)
#define SMEM_HALVES (2 * TM * HPITCH + 2 * TN * HPITCH)

__device__ __align__(16) __half g_a1[NB * ND];
__device__ __align__(16) __half g_a2[NB * ND];
__device__ float g_aux[(long)NB * NCOLT];    // per-(row, coltile) max of logits

__device__ __forceinline__ int fkey(float f) {
    int u = __float_as_int(f);
    return (u >= 0) ? u : (u ^ 0x7fffffff);
}
__device__ __forceinline__ float ikey(int k) {
    return (k >= 0) ? __int_as_float(k) : __int_as_float(k ^ 0x7fffffff);
}

__device__ __forceinline__ void mma16(float (&d)[4], const uint32_t (&a)[4],
                                      uint32_t b0, uint32_t b1) {
    asm("mma.sync.aligned.m16n8k16.row.col.f32.f16.f16.f32 "
        "{%0,%1,%2,%3}, {%4,%5,%6,%7}, {%8,%9}, {%0,%1,%2,%3};"
        : "+f"(d[0]), "+f"(d[1]), "+f"(d[2]), "+f"(d[3])
        : "r"(a[0]), "r"(a[1]), "r"(a[2]), "r"(a[3]), "r"(b0), "r"(b1));
}

__device__ __forceinline__ void ldsm4(uint32_t (&r)[4], uint32_t addr) {
    asm volatile("ldmatrix.sync.aligned.m8n8.x4.shared.b16 {%0,%1,%2,%3}, [%4];"
        : "=r"(r[0]), "=r"(r[1]), "=r"(r[2]), "=r"(r[3]) : "r"(addr));
}

__device__ __forceinline__ void hsplit(float a, __half& h1, __half& h2) {
    float w = a * SC;
    h1 = __float2half_rn(w);
    h2 = __float2half_rn(w - __half2float(h1));
}

// ---------------------------------------------------------------------------
// Kernel 1: ctx = mean(ctab[ids]) @ W + b, then scaled fp16 hi/lo split
// ---------------------------------------------------------------------------
__global__ void ctx_kernel(const int* __restrict__ ids,
                           const float* __restrict__ ctab,
                           const float* __restrict__ W,
                           const float* __restrict__ bias) {
    int row = blockIdx.x;
    int d = threadIdx.x;
    __shared__ float pooled[ND];

    float s = 0.0f;
    #pragma unroll 5
    for (int h = 0; h < NH; ++h) {
        int id = ids[row * NH + h];
        s += ctab[(long)id * ND + d];
    }
    pooled[d] = s * (1.0f / (float)NH);
    __syncthreads();

    float acc = bias[d];
    #pragma unroll 8
    for (int i = 0; i < ND; ++i)
        acc = fmaf(pooled[i], W[i * ND + d], acc);

    __half h1, h2;
    hsplit(acc, h1, h2);
    g_a1[row * ND + d] = h1;
    g_a2[row * ND + d] = h2;
}

// ---------------------------------------------------------------------------
// Kernel 2: logits = ctx @ labelT via 3x FP16 mma.sync (R12 engine).
// Edits vs R12: (1) B prefetch LDGs issued AFTER compute (pf live only
// across epilogue, not across the 215-reg compute loop);
// (2) tile-max reduced via shfl before smem atomics (4x fewer ATOMS).
// ---------------------------------------------------------------------------
extern __shared__ __half sm_h[];

__global__ __launch_bounds__(256, 1)
void gemm_kernel(const float* __restrict__ label, float* __restrict__ out) {
    const int tid  = threadIdx.x;
    const int lane = tid & 31;
    const int wid  = tid >> 5;
    const int r0   = blockIdx.y * TM;

    __shared__ int s_rowmax[TM];
    s_rowmax[tid] = 0x80000000;   // 256 threads, TM=256

    // ---- Load resident A rowtile (pre-split fp16): one row per thread ----
    {
        const uint4* p1 = (const uint4*)(g_a1 + (long)(r0 + tid) * ND);
        const uint4* p2 = (const uint4*)(g_a2 + (long)(r0 + tid) * ND);
        uint4* d1 = (uint4*)(sm_h + OFF_A1 + tid * HPITCH);
        uint4* d2 = (uint4*)(sm_h + OFF_A2 + tid * HPITCH);
        #pragma unroll
        for (int j = 0; j < 16; ++j) { d1[j] = p1[j]; d2[j] = p2[j]; }
    }

    // ---- Precompute per-thread ldmatrix base addresses (bytes) ----
    const uint32_t sbase = (uint32_t)__cvta_generic_to_shared(sm_h);
    uint32_t aA1[4], aA2[4], bB1[2], bB2[2];
    {
        int jrowA = ((lane >> 3) & 1) * 8 + (lane & 7);
        int kcolA = (lane >> 4) * 8;
        #pragma unroll
        for (int mi = 0; mi < 4; ++mi) {
            int rowA = (wid >> 1) * 64 + mi * 16 + jrowA;
            aA1[mi] = sbase + (uint32_t)(OFF_A1 + rowA * HPITCH + kcolA) * 2u;
            aA2[mi] = sbase + (uint32_t)(OFF_A2 + rowA * HPITCH + kcolA) * 2u;
        }
        int jrowB = (lane >> 4) * 8 + (lane & 7);
        int kcolB = ((lane >> 3) & 1) * 8;
        #pragma unroll
        for (int p = 0; p < 2; ++p) {
            int rowB = (wid & 1) * 32 + p * 16 + jrowB;
            bB1[p] = sbase + (uint32_t)(OFF_B1 + rowB * HPITCH + kcolB) * 2u;
            bB2[p] = sbase + (uint32_t)(OFF_B2 + rowB * HPITCH + kcolB) * 2u;
        }
    }

    // B prefetch mapping: thread covers vocab-row pn, float-cols pd + 16j
    const int pn = tid >> 2;
    const int pd = (tid & 3) * 4;
    float4 pf[8];

    auto ldg_tile = [&](int ctile) {
        long gn = (long)ctile * TN + pn;
        if (gn > NV - 1) gn = NV - 1;   // clamp; clamped tiles never consumed
        const float4* src = (const float4*)(label + gn * ND + pd);
        #pragma unroll
        for (int j = 0; j < 8; ++j) pf[j] = src[j * 4];
    };

    // ---- priming: load tile0 into pf ----
    int ct = blockIdx.x;
    ldg_tile(ct);

    while (true) {
        // ---- fill: split pf (tile ct) into fp16 b1/b2 smem ----
        __syncthreads();   // prior tile's frag reads done / rowmax reset visible
        {
            __half* b1 = sm_h + OFF_B1 + pn * HPITCH + pd;
            __half* b2 = sm_h + OFF_B2 + pn * HPITCH + pd;
            #pragma unroll
            for (int j = 0; j < 8; ++j) {
                float4 v = pf[j];
                __half hx1, hx2, hy1, hy2, hz1, hz2, hw1, hw2;
                hsplit(v.x, hx1, hx2); hsplit(v.y, hy1, hy2);
                hsplit(v.z, hz1, hz2); hsplit(v.w, hw1, hw2);
                __half2* q1 = (__half2*)(b1 + j * 16);
                __half2* q2 = (__half2*)(b2 + j * 16);
                q1[0] = __halves2half2(hx1, hy1);
                q1[1] = __halves2half2(hz1, hw1);
                q2[0] = __halves2half2(hx2, hy2);
                q2[1] = __halves2half2(hz2, hw2);
            }
        }
        __syncthreads();

        // ---- compute tile ct (register-double-buffered frags) ----
        uint32_t A1f[2][4][4], A2f[2][4][4], B1f[2][2][4], B2f[2][2][4];
        float acc[4][4][4];
        #pragma unroll
        for (int mi = 0; mi < 4; ++mi)
            #pragma unroll
            for (int ni = 0; ni < 4; ++ni)
                #pragma unroll
                for (int q = 0; q < 4; ++q) acc[mi][ni][q] = 0.0f;

        #pragma unroll
        for (int mi = 0; mi < 4; ++mi) { ldsm4(A1f[0][mi], aA1[mi]); ldsm4(A2f[0][mi], aA2[mi]); }
        ldsm4(B1f[0][0], bB1[0]); ldsm4(B1f[0][1], bB1[1]);
        ldsm4(B2f[0][0], bB2[0]); ldsm4(B2f[0][1], bB2[1]);

        #pragma unroll
        for (int ks = 0; ks < 8; ++ks) {
            const int kcur = ks & 1;
            if (ks < 7) {
                const int nxt = kcur ^ 1;
                const uint32_t ko = (uint32_t)(ks + 1) * 32u;   // 16 halves = 32 B
                #pragma unroll
                for (int mi = 0; mi < 4; ++mi) {
                    ldsm4(A1f[nxt][mi], aA1[mi] + ko);
                    ldsm4(A2f[nxt][mi], aA2[mi] + ko);
                }
                ldsm4(B1f[nxt][0], bB1[0] + ko); ldsm4(B1f[nxt][1], bB1[1] + ko);
                ldsm4(B2f[nxt][0], bB2[0] + ko); ldsm4(B2f[nxt][1], bB2[1] + ko);
            }
            #pragma unroll
            for (int mi = 0; mi < 4; ++mi)
                #pragma unroll
                for (int p = 0; p < 2; ++p) {
                    mma16(acc[mi][2*p],   A1f[kcur][mi], B1f[kcur][p][0], B1f[kcur][p][1]);
                    mma16(acc[mi][2*p+1], A1f[kcur][mi], B1f[kcur][p][2], B1f[kcur][p][3]);
                    mma16(acc[mi][2*p],   A1f[kcur][mi], B2f[kcur][p][0], B2f[kcur][p][1]);
                    mma16(acc[mi][2*p+1], A1f[kcur][mi], B2f[kcur][p][2], B2f[kcur][p][3]);
                    mma16(acc[mi][2*p],   A2f[kcur][mi], B1f[kcur][p][0], B1f[kcur][p][1]);
                    mma16(acc[mi][2*p+1], A2f[kcur][mi], B1f[kcur][p][2], B1f[kcur][p][3]);
                }
        }

        // ---- prefetch next tile AFTER compute: LDG latency hides under
        //      epilogue stores; pf not live across the compute loop ----
        const int nct = ct + NCG;
        const bool hasnext = (nct < NCOLT);
        if (hasnext) ldg_tile(nct);

        // ---- epilogue: un-scale (exact 2^-20), store, shfl-reduced tile max ----
        {
            const int n0 = ct * TN;
            #pragma unroll
            for (int mi = 0; mi < 4; ++mi) {
                int rloc0 = (wid >> 1) * 64 + mi * 16 + (lane >> 2);
                long rg = r0 + rloc0;
                float* o0 = out + rg * (long)NV;
                float* o1 = o0 + 8l * NV;
                float m0 = -FLT_MAX, m1 = -FLT_MAX;
                #pragma unroll
                for (int ni = 0; ni < 4; ++ni) {
                    int cg = n0 + (wid & 1) * 32 + ni * 8 + 2 * (lane & 3);
                    float v0 = acc[mi][ni][0] * ISC2, v1 = acc[mi][ni][1] * ISC2;
                    float v2 = acc[mi][ni][2] * ISC2, v3 = acc[mi][ni][3] * ISC2;
                    if (cg < NV) {
                        *(float2*)(o0 + cg) = make_float2(v0, v1);
                        *(float2*)(o1 + cg) = make_float2(v2, v3);
                    }
                    m0 = fmaxf(m0, fmaxf(v0, v1));
                    m1 = fmaxf(m1, fmaxf(v2, v3));
                }
                // reduce across the 4 lanes sharing each row (same lane>>2)
                m0 = fmaxf(m0, __shfl_xor_sync(0xffffffffu, m0, 1));
                m0 = fmaxf(m0, __shfl_xor_sync(0xffffffffu, m0, 2));
                m1 = fmaxf(m1, __shfl_xor_sync(0xffffffffu, m1, 1));
                m1 = fmaxf(m1, __shfl_xor_sync(0xffffffffu, m1, 2));
                if ((lane & 3) == 0) {
                    atomicMax(&s_rowmax[rloc0],     fkey(m0));
                    atomicMax(&s_rowmax[rloc0 + 8], fkey(m1));
                }
            }
        }
        __syncthreads();   // atomics done
        {
            g_aux[(long)(r0 + tid) * NCOLT + ct] = ikey(s_rowmax[tid]);
            s_rowmax[tid] = 0x80000000;
        }
        if (!hasnext) break;
        ct = nct;
        // loop-top __syncthreads() orders reset + frag reads vs refill
    }
}

// ---------------------------------------------------------------------------
// Kernel 3: pruned per-row top-10 using g_aux tile maxima.
// ---------------------------------------------------------------------------
#define T2 256

__global__ __launch_bounds__(T2)
void topk_kernel(const float* __restrict__ logits,
                 float* __restrict__ out_ids,
                 float* __restrict__ out_scores) {
    const int row = blockIdx.x;
    const int tid = threadIdx.x;

    __shared__ float sm[NCOLT];
    __shared__ float rv[T2];
    __shared__ int   ri[T2];
    __shared__ float tv[NK];
    __shared__ int   ti[NK];
    __shared__ float cand[TN];

    for (int j = tid; j < NCOLT; j += T2)
        sm[j] = g_aux[(long)row * NCOLT + j];
    if (tid < NK) { tv[tid] = -FLT_MAX; ti[tid] = 0; }
    __syncthreads();

    const float* lrow = logits + (long)row * NV;

    for (int round = 0; round < NCOLT; ++round) {
        float bv = -FLT_MAX; int bi = NCOLT;
        for (int j = tid; j < NCOLT; j += T2) {
            float v = sm[j];
            if (v > bv || (v == bv && j < bi)) { bv = v; bi = j; }
        }
        rv[tid] = bv; ri[tid] = bi;
        __syncthreads();
        #pragma unroll
        for (int s = T2 / 2; s > 0; s >>= 1) {
            if (tid < s) {
                float ov = rv[tid + s]; int oi = ri[tid + s];
                if (ov > rv[tid] || (ov == rv[tid] && oi < ri[tid])) {
                    rv[tid] = ov; ri[tid] = oi;
                }
            }
            __syncthreads();
        }
        float best = rv[0]; int bidx = ri[0];
        if (best < tv[NK - 1] || bidx >= NCOLT) break;

        if (tid < TN) {
            int c = bidx * TN + tid;
            cand[tid] = (c < NV) ? lrow[c] : -FLT_MAX;
        }
        __syncthreads();
        if (tid == 0) {
            #pragma unroll 4
            for (int c = 0; c < TN; ++c) {
                float v = cand[c];
                int   id = bidx * TN + c;
                if (v > tv[NK - 1] || (v == tv[NK - 1] && v > -FLT_MAX && id < ti[NK - 1])) {
                    tv[NK - 1] = v; ti[NK - 1] = id;
                    #pragma unroll
                    for (int j = NK - 1; j > 0; --j) {
                        bool sw = (tv[j] > tv[j - 1]) ||
                                  (tv[j] == tv[j - 1] && ti[j] < ti[j - 1]);
                        if (sw) {
                            float fv = tv[j]; tv[j] = tv[j - 1]; tv[j - 1] = fv;
                            int ii = ti[j]; ti[j] = ti[j - 1]; ti[j - 1] = ii;
                        }
                    }
                }
            }
            sm[bidx] = -FLT_MAX;
        }
        __syncthreads();
    }

    if (tid < NK) {
        out_ids[row * NK + tid]    = (float)ti[tid];
        out_scores[row * NK + tid] = tv[tid];
    }
}

// ---------------------------------------------------------------------------
// Launch
// ---------------------------------------------------------------------------
extern "C" void kernel_launch(void* const* d_in, const int* in_sizes, int n_in,
                              void* d_out, int out_size) {
    const int*   ids  = (const int*)d_in[0];
    const float* ctab = (const float*)d_in[1];
    const float* ltab = (const float*)d_in[2];
    const float* W    = (const float*)d_in[3];
    const float* bias = (const float*)d_in[4];

    float* out        = (float*)d_out;
    float* logits     = out;
    float* out_ids    = out + (long)NB * NV;
    float* out_scores = out_ids + NB * NK;

    ctx_kernel<<<NB, ND>>>(ids, ctab, W, bias);

    size_t smem = (size_t)SMEM_HALVES * 2;   // 174080 B
    cudaFuncSetAttribute(gemm_kernel, cudaFuncAttributeMaxDynamicSharedMemorySize, (int)smem);
    dim3 grid(NCG, NRT);
    gemm_kernel<<<grid, 256, smem>>>(ltab, logits);

    topk_kernel<<<NB, T2>>>(logits, out_ids, out_scores);
}